// round 13
// baseline (speedup 1.0000x reference)
#include <cuda_runtime.h>
#include <cuda_fp16.h>

#define S_LEN 4096
#define TWO_PI_F 6.28318530717958647692f

typedef unsigned long long u64;

// fp16 transposed weights [j][i]; fp32 cP
__device__ float  g_cPt[64 * 64];      // fp32 [j][i]
__device__ __half g_M1h[64 * 128];
__device__ __half g_R1h[64 * 128];
__device__ __half g_M2h[128 * 128];
__device__ __half g_P1h[128 * 128];
__device__ __half g_P2h[128 * 128];

__global__ void prep_kernel(
    const float* __restrict__ cP, const float* __restrict__ M1,
    const float* __restrict__ R1, const float* __restrict__ M2,
    const float* __restrict__ P1, const float* __restrict__ P2)
{
    int t = blockIdx.x * blockDim.x + threadIdx.x;
    if (t < 16384) {
        int i = t >> 7, j = t & 127;
        g_M2h[j * 128 + i] = __float2half_rn(M2[t]);
        g_P1h[j * 128 + i] = __float2half_rn(P1[t]);
        g_P2h[j * 128 + i] = __float2half_rn(P2[t]);
    }
    if (t < 8192) {
        int i = t >> 6, j = t & 63;
        g_M1h[j * 128 + i] = __float2half_rn(M1[t]);
        g_R1h[j * 128 + i] = __float2half_rn(R1[t]);
    }
    if (t < 4096) {
        int i = t >> 6, j = t & 63;
        g_cPt[j * 64 + i] = cP[t];
    }
}

// ~0.5-ulp reciprocal: rcp.approx + one Newton step
__device__ __forceinline__ float rcp_nr(float x)
{
    float r; asm("rcp.approx.f32 %0, %1;" : "=f"(r) : "f"(x));
    float e = fmaf(-x, r, 1.0f);
    return fmaf(r, e, r);
}

// cos(2*pi*s/p): rp computed in-register, exact-frac via fma, __cosf on [-pi,pi]
__device__ __forceinline__ float pcosp(float sf, float pf)
{
    float rp = rcp_nr(pf);
    float f = sf * rp;
    float n = rintf(f);
    float r = fmaf(sf, rp, -n);
    return __cosf(TWO_PI_F * r);
}

// ---- packed f32x2 helpers; payload in u64 ----
__device__ __forceinline__ u64 fma2(u64 a, u64 b, u64 c)
{ u64 d; asm("fma.rn.f32x2 %0, %1, %2, %3;" : "=l"(d) : "l"(a), "l"(b), "l"(c)); return d; }
__device__ __forceinline__ u64 mul2(u64 a, u64 b)
{ u64 d; asm("mul.rn.f32x2 %0, %1, %2;" : "=l"(d) : "l"(a), "l"(b)); return d; }
__device__ __forceinline__ u64 add2(u64 a, u64 b)
{ u64 d; asm("add.rn.f32x2 %0, %1, %2;" : "=l"(d) : "l"(a), "l"(b)); return d; }
__device__ __forceinline__ u64 bcast2(float x)
{ u64 d; asm("mov.b64 %0, {%1, %1};" : "=l"(d) : "f"(x)); return d; }
__device__ __forceinline__ u64 f2d(float2 v)
{ u64 d; asm("mov.b64 %0, {%1, %2};" : "=l"(d) : "f"(v.x), "f"(v.y)); return d; }
__device__ __forceinline__ float2 d2f(u64 d)
{ float2 v; asm("mov.b64 {%0, %1}, %2;" : "=f"(v.x), "=f"(v.y) : "l"(d)); return v; }

__device__ __forceinline__ float warpsum(float v)
{
#pragma unroll
    for (int o = 16; o > 0; o >>= 1) v += __shfl_xor_sync(0xffffffffu, v, o);
    return v;
}

// smem layout (float index units)
#define OFF_PHI  0          // 16384 halves = 8192 floats
#define OFF_PART 8192       // 2048 u64 = 4096 floats
#define OFF_XST  12288      // 256
#define OFF_HST  12544      // 256
#define OFF_LN1  12800      // 512
#define OFF_H1S  13312      // 512
#define OFF_LN2  13824      // 512
#define OFF_WSM  14336      // 16
#define OFF_WSQ  14352      // 16
#define SM_FLOATS 14368
#define SMEM_BYTES (SM_FLOATS * 4)

// fp16-weight step: one j, 4 batches x 2 i (i-pair) via 4 f32x2 FMAs
#define WSTEP8(W, ACT, J) {                                             \
    unsigned wu = *(const unsigned*)&W[(J) * 128 + 2 * i2];             \
    u64 wd = f2d(__half22float2(*(__half2*)&wu));                       \
    float4 a = *(const float4*)&ACT[(J) * 4];                           \
    A0 = fma2(wd, bcast2(a.x), A0);                                     \
    A1 = fma2(wd, bcast2(a.y), A1);                                     \
    A2 = fma2(wd, bcast2(a.z), A2);                                     \
    A3 = fma2(wd, bcast2(a.w), A3); }

// phase-modulated fp16-weight step
#define PSTEP8(W, ACT, J) {                                             \
    unsigned wu = *(const unsigned*)&W[(J) * 128 + 2 * i2];             \
    unsigned pu = *(const unsigned*)&phi16[(J) * 128 + 2 * i2];         \
    u64 wd = mul2(f2d(__half22float2(*(__half2*)&wu)),                  \
                  f2d(__half22float2(*(__half2*)&pu)));                 \
    float4 a = *(const float4*)&ACT[(J) * 4];                           \
    A0 = fma2(wd, bcast2(a.x), A0);                                     \
    A1 = fma2(wd, bcast2(a.y), A1);                                     \
    A2 = fma2(wd, bcast2(a.z), A2);                                     \
    A3 = fma2(wd, bcast2(a.w), A3); }

#define DECL_ACC u64 A0 = 0, A1 = 0, A2 = 0, A3 = 0;

// partials layout: [js][b][i2] u64, js<8, b<4, i2<64
#define STOREP8() {                                                     \
    partd[js8 * 256 + 0 * 64 + i2] = A0;                                \
    partd[js8 * 256 + 1 * 64 + i2] = A1;                                \
    partd[js8 * 256 + 2 * 64 + i2] = A2;                                \
    partd[js8 * 256 + 3 * 64 + i2] = A3; }

__global__ __launch_bounds__(512, 2)
void hier_kernel(const int*   __restrict__ tokens,
                 const int*   __restrict__ positions,
                 const float* __restrict__ emb,
                 const float* __restrict__ g1, const float* __restrict__ b1,
                 const float* __restrict__ g2, const float* __restrict__ b2,
                 float*       __restrict__ out)
{
    extern __shared__ __align__(16) float sm[];
    __half* phi16 = (__half*)(sm + OFF_PHI);     // [j][i] 128x128
    u64*    partd = (u64*)(sm + OFF_PART);       // [js][b][i2]
    float*  xsT   = sm + OFF_XST;                // [j][4b]
    float*  hsT   = sm + OFF_HST;                // [j][4b]
    float*  ln1T  = sm + OFF_LN1;                // [j][4b]
    float*  h1sT  = sm + OFF_H1S;                // [j][4b]
    float*  ln2T  = sm + OFF_LN2;                // [j][4b]
    float*  wsm   = sm + OFF_WSM;
    float*  wsq   = sm + OFF_WSQ;

    const int tid = threadIdx.x;
    const int s   = blockIdx.x;
    const float sf = (float)positions[s];

    // ---- build fp16 phiD[j][i]; periods computed in-register ----
    // k = j*128 + i ; period = i*128 + j + 2 ; 4 consecutive k -> +128 steps
#pragma unroll
    for (int n = 0; n < 8; ++n) {
        int k = n * 2048 + tid * 4;
        float p0 = (float)((k & 127) * 128 + (k >> 7) + 2);
        __half2 h0 = __floats2half2_rn(pcosp(sf, p0),          pcosp(sf, p0 + 128.f));
        __half2 h1 = __floats2half2_rn(pcosp(sf, p0 + 256.f),  pcosp(sf, p0 + 384.f));
        union { uint2 u; __half2 h[2]; } pk;
        pk.h[0] = h0; pk.h[1] = h1;
        *(uint2*)&phi16[k] = pk.u;
    }

    // ---- gather embeddings: xsT[j][b] ----
    if (tid < 256) {
        int b0 = tid >> 6, j0 = tid & 63;
        int tok = tokens[b0 * S_LEN + s];
        xsT[j0 * 4 + b0] = emb[tok * 64 + j0];
    }
    __syncthreads();

    // =====================================================================
    // Layer 0 (V=64): 64 i x 8 j-slices of 8, f32x2 over batch pairs
    // =====================================================================
    {
        const int i = tid & 63, sl = tid >> 6;
        const float pbase = (float)(i * 64 + 2);
        u64 a01 = 0, a23 = 0;
#pragma unroll
        for (int jj = 0; jj < 8; ++jj) {
            int j = sl * 8 + jj;
            float pw = g_cPt[j * 64 + i] * pcosp(sf, pbase + (float)j);
            u64 p2 = bcast2(pw);
            float4 a = *(const float4*)&xsT[j * 4];
            ulonglong2 ad = *(ulonglong2*)&a;
            a01 = fma2(p2, ad.x, a01);
            a23 = fma2(p2, ad.y, a23);
        }
        ulonglong2 st; st.x = a01; st.y = a23;
        *(ulonglong2*)&partd[sl * 128 + i * 2] = st;
    }
    __syncthreads();
    if (tid < 128) {
        int i = tid >> 1, pp = tid & 1;
        u64 v = 0;
#pragma unroll
        for (int sl = 0; sl < 8; ++sl) v = add2(v, partd[sl * 128 + i * 2 + pp]);
        float2 f = d2f(v);
        hsT[i * 4 + pp * 2 + 0] = f.x;
        hsT[i * 4 + pp * 2 + 1] = f.y;
    }
    __syncthreads();

    // D-stage mapping: warp = (i-half, j-slice); lane carries i-pair
    const int w    = tid >> 5;
    const int ih   = w & 1;
    const int js8  = w >> 1;                 // 0..7
    const int i2   = ih * 32 + (tid & 31);   // i-pair 0..63
    // reduce mapping (tid < 256): b, i-pair
    const int rb   = tid >> 6;               // 0..3
    const int ri2  = tid & 63;

    // =====================================================================
    // t1 = M1 @ h : 64 j, slice of 8
    // =====================================================================
    {
        DECL_ACC;
        const int j0 = js8 * 8;
#pragma unroll
        for (int k = 0; k < 8; ++k) WSTEP8(g_M1h, hsT, j0 + k);
        STOREP8();
    }
    __syncthreads();

    // ---- reduce t1 + LayerNorm 1 ----
    if (tid < 256) {
        u64 v = 0;
#pragma unroll
        for (int sl = 0; sl < 8; ++sl)
            v = add2(v, partd[sl * 256 + rb * 64 + ri2]);
        float2 f = d2f(v);
        float sm_ = warpsum(f.x + f.y);
        float sq_ = warpsum(fmaf(f.x, f.x, f.y * f.y));
        if ((tid & 31) == 0) { wsm[tid >> 5] = sm_; wsq[tid >> 5] = sq_; }
        partd[1792 + rb * 64 + ri2] = v;   // stash (slice-7 slot free after read)
    }
    __syncthreads();
    if (tid < 256) {
        float mean = (wsm[rb * 2] + wsm[rb * 2 + 1]) * 0.0078125f;
        float ex2  = (wsq[rb * 2] + wsq[rb * 2 + 1]) * 0.0078125f;
        float rstd = rsqrtf(fmaf(-mean, mean, ex2) + 1e-5f);
        float2 f = d2f(partd[1792 + rb * 64 + ri2]);
        float2 gg = *(const float2*)&g1[ri2 * 2];
        float2 bb = *(const float2*)&b1[ri2 * 2];
        ln1T[(2 * ri2)     * 4 + rb] = (f.x - mean) * rstd * gg.x + bb.x;
        ln1T[(2 * ri2 + 1) * 4 + rb] = (f.y - mean) * rstd * gg.y + bb.y;
    }
    __syncthreads();

    // =====================================================================
    // h1 = posnk(ln1, P1, phiD) + R1 @ h : 16 j (P) + 8 j (R) per slice
    // =====================================================================
    {
        DECL_ACC;
        const int j0 = js8 * 16;
#pragma unroll
        for (int k = 0; k < 16; ++k) PSTEP8(g_P1h, ln1T, j0 + k);
        const int jr = js8 * 8;
#pragma unroll
        for (int k = 0; k < 8; ++k) WSTEP8(g_R1h, hsT, jr + k);
        STOREP8();
    }
    __syncthreads();
    if (tid < 256) {
        u64 v = 0;
#pragma unroll
        for (int sl = 0; sl < 8; ++sl)
            v = add2(v, partd[sl * 256 + rb * 64 + ri2]);
        float2 f = d2f(v);
        h1sT[(2 * ri2)     * 4 + rb] = f.x;
        h1sT[(2 * ri2 + 1) * 4 + rb] = f.y;
    }
    __syncthreads();

    // =====================================================================
    // t2 = M2 @ h1 : 16 j per slice
    // =====================================================================
    {
        DECL_ACC;
        const int j0 = js8 * 16;
#pragma unroll
        for (int k = 0; k < 16; ++k) WSTEP8(g_M2h, h1sT, j0 + k);
        STOREP8();
    }
    __syncthreads();

    // ---- reduce t2 + LayerNorm 2 (t2 pair kept in register for residual) ----
    u64 t2d = 0;
    if (tid < 256) {
#pragma unroll
        for (int sl = 0; sl < 8; ++sl)
            t2d = add2(t2d, partd[sl * 256 + rb * 64 + ri2]);
        float2 f = d2f(t2d);
        float sm_ = warpsum(f.x + f.y);
        float sq_ = warpsum(fmaf(f.x, f.x, f.y * f.y));
        if ((tid & 31) == 0) { wsm[tid >> 5] = sm_; wsq[tid >> 5] = sq_; }
    }
    __syncthreads();
    if (tid < 256) {
        float mean = (wsm[rb * 2] + wsm[rb * 2 + 1]) * 0.0078125f;
        float ex2  = (wsq[rb * 2] + wsq[rb * 2 + 1]) * 0.0078125f;
        float rstd = rsqrtf(fmaf(-mean, mean, ex2) + 1e-5f);
        float2 f = d2f(t2d);
        float2 gg = *(const float2*)&g2[ri2 * 2];
        float2 bb = *(const float2*)&b2[ri2 * 2];
        ln2T[(2 * ri2)     * 4 + rb] = (f.x - mean) * rstd * gg.x + bb.x;
        ln2T[(2 * ri2 + 1) * 4 + rb] = (f.y - mean) * rstd * gg.y + bb.y;
    }
    __syncthreads();

    // =====================================================================
    // out = posnk(ln2, P2, phiD) + t2
    // =====================================================================
    {
        DECL_ACC;
        const int j0 = js8 * 16;
#pragma unroll
        for (int k = 0; k < 16; ++k) PSTEP8(g_P2h, ln2T, j0 + k);
        STOREP8();
    }
    __syncthreads();
    if (tid < 256) {
        u64 v = t2d;
#pragma unroll
        for (int sl = 0; sl < 8; ++sl)
            v = add2(v, partd[sl * 256 + rb * 64 + ri2]);
        float2 f = d2f(v);
        *(float2*)&out[((size_t)rb * S_LEN + s) * 128 + 2 * ri2] = f;
    }
}

extern "C" void kernel_launch(void* const* d_in, const int* in_sizes, int n_in,
                              void* d_out, int out_size)
{
    const int*   tokens    = (const int*)  d_in[0];
    const int*   positions = (const int*)  d_in[1];
    const float* emb       = (const float*)d_in[2];
    const float* char_P    = (const float*)d_in[3];
    const float* M1        = (const float*)d_in[4];
    const float* P1        = (const float*)d_in[5];
    const float* g1        = (const float*)d_in[6];
    const float* b1        = (const float*)d_in[7];
    const float* R1        = (const float*)d_in[8];
    const float* M2        = (const float*)d_in[9];
    const float* P2        = (const float*)d_in[10];
    const float* g2        = (const float*)d_in[11];
    const float* b2        = (const float*)d_in[12];
    float* out = (float*)d_out;

    cudaFuncSetAttribute(hier_kernel,
                         cudaFuncAttributeMaxDynamicSharedMemorySize, SMEM_BYTES);

    prep_kernel<<<32, 512>>>(char_P, M1, R1, M2, P1, P2);
    hier_kernel<<<S_LEN, 512, SMEM_BYTES>>>(tokens, positions, emb,
                                            g1, b1, g2, b2, out);
}